// round 11
// baseline (speedup 1.0000x reference)
#include <cuda_runtime.h>

#define NPIX 65536
#define CIN 128
#define NH 4
#define NT 4
#define OD 512            // NH * 128 folded dimension
#define TILE 32           // pixels per block (halved: 2 CTAs/SM)
#define NTHREADS 256
#define ZST 36            // zsT row stride: 144B, 16B-aligned for float4 reads
#define UST 516           // Us row stride (mod 32 == 4 -> conflict-free phase 2)
#define CHUNK_FLOATS 2048 // 4 rows x 512 (phase 1) / 16 rows x 128 (phase 3)
#define SMEM_FLOATS (CIN*ZST + TILE*UST + 2*CHUNK_FLOATS)
#define SCALE 0.08838834764831845f   // 1/sqrt(128)

// Folded weights (precomputed each call; no caching)
__device__ float g_Mcat[CIN*OD];   // [c1][o], o = h*128 + c2 : Wq_h^T Wk_h
__device__ float g_Pcat[OD*CIN];   // [o][d]                  : Wo_h Wv_h

__global__ void precompute_MP(const float* __restrict__ Wq, const float* __restrict__ Wk,
                              const float* __restrict__ Wv, const float* __restrict__ Wo) {
    int idx = blockIdx.x * blockDim.x + threadIdx.x;
    if (idx >= CIN*OD) return;
    {
        int c1 = idx >> 9;
        int o  = idx & (OD-1);
        int h = o >> 7, c2 = o & 127;
        float s = 0.f;
        #pragma unroll 4
        for (int cc = 0; cc < 64; cc++) {
            int row = (cc*4 + h) * CIN;
            s += Wq[row + c1] * Wk[row + c2];
        }
        g_Mcat[idx] = s;
    }
    {
        int o = idx >> 7;
        int d = idx & 127;
        int h = o >> 7, c2 = o & 127;
        float s = 0.f;
        #pragma unroll 4
        for (int cc = 0; cc < 64; cc++) {
            int ch = cc*4 + h;
            s += Wo[d*256 + ch] * Wv[ch*CIN + c2];
        }
        g_Pcat[idx] = s;
    }
}

__device__ __forceinline__ unsigned long long pack2(float x) {
    unsigned long long r;
    asm("mov.b64 %0, {%1, %1};" : "=l"(r) : "f"(x));
    return r;
}
__device__ __forceinline__ void fma2(unsigned long long &d, unsigned long long a, unsigned long long b) {
    asm("fma.rn.f32x2 %0, %1, %2, %0;" : "+l"(d) : "l"(a), "l"(b));
}
__device__ __forceinline__ void cp16(float* dst, const float* src) {
    unsigned s = (unsigned)__cvta_generic_to_shared(dst);
    asm volatile("cp.async.cg.shared.global [%0], [%1], 16;" :: "r"(s), "l"(src));
}
#define CP_COMMIT() asm volatile("cp.async.commit_group;")
#define CP_WAIT0()  asm volatile("cp.async.wait_group 0;")

__global__ void __launch_bounds__(NTHREADS, 2)
attn_fused(const float* __restrict__ z2d, const float* __restrict__ t2d,
           const float* __restrict__ bo, float* __restrict__ out)
{
    extern __shared__ float sm[];
    float* zsT = sm;                       // [CIN][ZST]  transposed z tile
    float* Us  = sm + CIN*ZST;             // [TILE][UST] U, later zbar (in place)
    float* bufA = Us + TILE*UST;           // double-buffered weight chunks
    float* bufB = bufA + CHUNK_FLOATS;

    const int tid = threadIdx.x;
    const int p0  = blockIdx.x * TILE;

    // ---- load z tile, transposed ----
    {
        const float* zsrc = z2d + (long)p0 * CIN;
        #pragma unroll
        for (int i = 0; i < TILE*CIN/NTHREADS; i++) {
            int idx = tid + i*NTHREADS;
            int px = idx >> 7, c = idx & 127;
            zsT[c*ZST + px] = zsrc[idx];
        }
    }
    // prefetch M chunk 0
    cp16(bufA + tid*4, g_Mcat + tid*4);
    cp16(bufA + tid*4 + 1024, g_Mcat + tid*4 + 1024);
    CP_COMMIT();

    const int pixgrp = tid >> 6;   // 0..3 -> 8 pixels each
    const int lsub   = tid & 63;   // column-pair owner

    // ---- phase 1: U[32][512] = Z[32][128] @ Mcat[128][512] ----
    unsigned long long acc[32];    // [px 8][head 4] f32x2 pairs at o = k*128 + 2*lsub
    #pragma unroll
    for (int i = 0; i < 32; i++) acc[i] = 0ull;

    for (int c = 0; c < 32; c++) {          // 32 chunks of 4 k-rows
        CP_WAIT0();
        __syncthreads();                     // chunk c resident; prev buffer free
        float* bufh = (c & 1) ? bufB : bufA;
        if (c < 31) {
            float* nxt = (c & 1) ? bufA : bufB;
            const float* src = g_Mcat + (c+1)*CHUNK_FLOATS;
            cp16(nxt + tid*4, src + tid*4);
            cp16(nxt + tid*4 + 1024, src + tid*4 + 1024);
            CP_COMMIT();
        }
        #pragma unroll
        for (int kk = 0; kk < 4; kk++) {
            const float* zrow = zsT + (c*4+kk)*ZST + pixgrp*8;
            float4 za  = *(const float4*)(zrow);
            float4 zbv = *(const float4*)(zrow + 4);
            unsigned long long zz[8];
            zz[0]=pack2(za.x);  zz[1]=pack2(za.y);  zz[2]=pack2(za.z);  zz[3]=pack2(za.w);
            zz[4]=pack2(zbv.x); zz[5]=pack2(zbv.y); zz[6]=pack2(zbv.z); zz[7]=pack2(zbv.w);
            const float* mrow = bufh + kk*OD + 2*lsub;
            #pragma unroll
            for (int k = 0; k < 4; k++) {
                unsigned long long mv = *(const unsigned long long*)(mrow + k*128);
                #pragma unroll
                for (int px = 0; px < 8; px++)
                    fma2(acc[px*4 + k], zz[px], mv);
            }
        }
    }
    #pragma unroll
    for (int px = 0; px < 8; px++) {
        float* urow = Us + (pixgrp*8 + px)*UST + 2*lsub;
        #pragma unroll
        for (int k = 0; k < 4; k++)
            *(unsigned long long*)(urow + k*128) = acc[px*4 + k];
    }
    __syncthreads();   // U complete; all phase-1 reads of bufA/bufB done

    // prefetch P chunk 0 into bufA — rides under all of phase 2
    cp16(bufA + tid*4, g_Pcat + tid*4);
    cp16(bufA + tid*4 + 1024, g_Pcat + tid*4 + 1024);
    CP_COMMIT();

    // ---- phase 2: scores (U . z_t), softmax over t, zbar -> Us (in place) ----
    {
        const int lane = tid & 31;
        const int pix  = (tid >> 5) * 4 + (lane & 3);  // 0..31, conflict-free LDS map
        const int sub  = lane >> 2;                    // 0..7, in-warp reduction group
        const int cb   = sub * 16;
        const float* zt0 = t2d + (long)(p0 + pix) * CIN + cb;

        float s[NT][NH];
        #pragma unroll
        for (int t = 0; t < NT; t++)
            #pragma unroll
            for (int h = 0; h < NH; h++) s[t][h] = 0.f;

        #pragma unroll
        for (int q4 = 0; q4 < 4; q4++) {
            float4 zl[NT];
            #pragma unroll
            for (int t = 0; t < NT; t++)
                zl[t] = *(const float4*)(zt0 + (long)t * NPIX * CIN + q4*4);
            #pragma unroll
            for (int h = 0; h < NH; h++) {
                float4 u = *(const float4*)(Us + pix*UST + h*128 + cb + q4*4);
                #pragma unroll
                for (int t = 0; t < NT; t++)
                    s[t][h] += u.x*zl[t].x + u.y*zl[t].y + u.z*zl[t].z + u.w*zl[t].w;
            }
        }
        #pragma unroll
        for (int t = 0; t < NT; t++)
            #pragma unroll
            for (int h = 0; h < NH; h++) {
                float p = s[t][h];
                p += __shfl_xor_sync(0xffffffffu, p, 4);
                p += __shfl_xor_sync(0xffffffffu, p, 8);
                p += __shfl_xor_sync(0xffffffffu, p, 16);
                s[t][h] = p * SCALE;
            }
        float w[NT][NH];
        #pragma unroll
        for (int h = 0; h < NH; h++) {
            float m = fmaxf(fmaxf(s[0][h], s[1][h]), fmaxf(s[2][h], s[3][h]));
            float e0 = __expf(s[0][h]-m), e1 = __expf(s[1][h]-m);
            float e2 = __expf(s[2][h]-m), e3 = __expf(s[3][h]-m);
            float inv = 1.f / (e0+e1+e2+e3);
            w[0][h]=e0*inv; w[1][h]=e1*inv; w[2][h]=e2*inv; w[3][h]=e3*inv;
        }
        float zb[NH][16];
        #pragma unroll
        for (int h = 0; h < NH; h++)
            #pragma unroll
            for (int q = 0; q < 16; q++) zb[h][q] = 0.f;
        #pragma unroll
        for (int t = 0; t < NT; t++) {
            const float* ztp = zt0 + (long)t * NPIX * CIN;   // L1 hit (second read)
            float4 zl[4];
            #pragma unroll
            for (int q4 = 0; q4 < 4; q4++) zl[q4] = *(const float4*)(ztp + q4*4);
            #pragma unroll
            for (int h = 0; h < NH; h++) {
                float wv = w[t][h];
                #pragma unroll
                for (int q4 = 0; q4 < 4; q4++) {
                    zb[h][q4*4+0] = fmaf(wv, zl[q4].x, zb[h][q4*4+0]);
                    zb[h][q4*4+1] = fmaf(wv, zl[q4].y, zb[h][q4*4+1]);
                    zb[h][q4*4+2] = fmaf(wv, zl[q4].z, zb[h][q4*4+2]);
                    zb[h][q4*4+3] = fmaf(wv, zl[q4].w, zb[h][q4*4+3]);
                }
            }
        }
        #pragma unroll
        for (int h = 0; h < NH; h++) {
            float* urow = Us + pix*UST + h*128 + cb;
            #pragma unroll
            for (int q4 = 0; q4 < 4; q4++)
                *(float4*)(urow + q4*4) = make_float4(zb[h][q4*4+0], zb[h][q4*4+1],
                                                      zb[h][q4*4+2], zb[h][q4*4+3]);
        }
    }

    // ---- phase 3: out[32][128] = zbar[32][512] @ Pcat[512][128] + bo ----
    {
        unsigned long long oacc[8];
        unsigned long long bo2 = *(const unsigned long long*)(bo + 2*lsub);
        #pragma unroll
        for (int px = 0; px < 8; px++) oacc[px] = bo2;

        for (int c = 0; c < 32; c++) {      // 32 chunks of 16 P-rows
            CP_WAIT0();
            __syncthreads();                 // chunk c resident; zbar visible (c==0)
            float* bufh = (c & 1) ? bufB : bufA;
            if (c < 31) {
                float* nxt = (c & 1) ? bufA : bufB;
                const float* src = g_Pcat + (c+1)*CHUNK_FLOATS;
                cp16(nxt + tid*4, src + tid*4);
                cp16(nxt + tid*4 + 1024, src + tid*4 + 1024);
                CP_COMMIT();
            }
            const int o0 = c * 16;
            #pragma unroll
            for (int og = 0; og < 4; og++) {
                unsigned long long pm[4];
                #pragma unroll
                for (int r = 0; r < 4; r++)
                    pm[r] = *(const unsigned long long*)(bufh + (og*4+r)*CIN + 2*lsub);
                #pragma unroll
                for (int px = 0; px < 8; px++) {
                    const float4 zq = *(const float4*)(Us + (pixgrp*8+px)*UST + o0 + og*4);
                    fma2(oacc[px], pack2(zq.x), pm[0]);
                    fma2(oacc[px], pack2(zq.y), pm[1]);
                    fma2(oacc[px], pack2(zq.z), pm[2]);
                    fma2(oacc[px], pack2(zq.w), pm[3]);
                }
            }
        }
        #pragma unroll
        for (int px = 0; px < 8; px++) {
            long p = p0 + pixgrp*8 + px;
            *(unsigned long long*)(out + p*CIN + 2*lsub) = oacc[px];
        }
    }
}

extern "C" void kernel_launch(void* const* d_in, const int* in_sizes, int n_in,
                              void* d_out, int out_size) {
    const float* z2d = (const float*)d_in[0];
    const float* t2d = (const float*)d_in[1];
    const float* Wq  = (const float*)d_in[2];
    const float* Wk  = (const float*)d_in[3];
    const float* Wv  = (const float*)d_in[4];
    const float* Wo  = (const float*)d_in[5];
    const float* bo  = (const float*)d_in[6];
    float* out = (float*)d_out;

    precompute_MP<<<(CIN*OD + 255)/256, 256>>>(Wq, Wk, Wv, Wo);

    cudaFuncSetAttribute(attn_fused, cudaFuncAttributeMaxDynamicSharedMemorySize,
                         SMEM_FLOATS * (int)sizeof(float));
    attn_fused<<<NPIX/TILE, NTHREADS, SMEM_FLOATS * sizeof(float)>>>(z2d, t2d, bo, out);
}

// round 12
// speedup vs baseline: 1.0554x; 1.0554x over previous
#include <cuda_runtime.h>

#define NPIX 65536
#define CIN 128
#define NH 4
#define NT 4
#define OD 512            // NH * 128 folded dimension
#define TILE 64           // pixels per block
#define NTHREADS 512
#define ZST 68            // zsT row stride (16B-aligned rows)
#define UST 516           // Us row stride
#define CHUNK_FLOATS 4096 // 8 rows x 512 (phase 1) / 32 rows x 128 (phase 3)
#define SMEM_FLOATS (CIN*ZST + TILE*UST + 2*CHUNK_FLOATS)
#define SCALE 0.08838834764831845f   // 1/sqrt(128)

// Folded weights (precomputed each call; no caching)
__device__ float g_Mcat[CIN*OD];   // [c1][o], o = h*128 + c2 : Wq_h^T Wk_h
__device__ float g_Pcat[OD*CIN];   // [o][d]                  : Wo_h Wv_h

__global__ void precompute_MP(const float* __restrict__ Wq, const float* __restrict__ Wk,
                              const float* __restrict__ Wv, const float* __restrict__ Wo) {
    int idx = blockIdx.x * blockDim.x + threadIdx.x;
    if (idx >= CIN*OD) return;
    {
        int c1 = idx >> 9;
        int o  = idx & (OD-1);
        int h = o >> 7, c2 = o & 127;
        float s = 0.f;
        #pragma unroll 4
        for (int cc = 0; cc < 64; cc++) {
            int row = (cc*4 + h) * CIN;
            s += Wq[row + c1] * Wk[row + c2];
        }
        g_Mcat[idx] = s;
    }
    {
        int o = idx >> 7;
        int d = idx & 127;
        int h = o >> 7, c2 = o & 127;
        float s = 0.f;
        #pragma unroll 4
        for (int cc = 0; cc < 64; cc++) {
            int ch = cc*4 + h;
            s += Wo[d*256 + ch] * Wv[ch*CIN + c2];
        }
        g_Pcat[idx] = s;
    }
}

__device__ __forceinline__ unsigned long long pack2(float x) {
    unsigned long long r;
    asm("mov.b64 %0, {%1, %1};" : "=l"(r) : "f"(x));
    return r;
}
__device__ __forceinline__ void fma2(unsigned long long &d, unsigned long long a, unsigned long long b) {
    asm("fma.rn.f32x2 %0, %1, %2, %0;" : "+l"(d) : "l"(a), "l"(b));
}
__device__ __forceinline__ unsigned long long add2(unsigned long long a, unsigned long long b) {
    unsigned long long r;
    asm("add.rn.f32x2 %0, %1, %2;" : "=l"(r) : "l"(a), "l"(b));
    return r;
}
__device__ __forceinline__ void cp16(float* dst, const float* src) {
    unsigned s = (unsigned)__cvta_generic_to_shared(dst);
    asm volatile("cp.async.cg.shared.global [%0], [%1], 16;" :: "r"(s), "l"(src));
}
#define CP_COMMIT() asm volatile("cp.async.commit_group;")
#define CP_WAIT0()  asm volatile("cp.async.wait_group 0;")

__global__ void __launch_bounds__(NTHREADS, 1)
attn_fused(const float* __restrict__ z2d, const float* __restrict__ t2d,
           const float* __restrict__ bo, float* __restrict__ out)
{
    extern __shared__ float sm[];
    float* zsT = sm;                       // [CIN][ZST]  transposed z tile; reused as reduction buf in phase 3
    float* Us  = sm + CIN*ZST;             // [TILE][UST] U, later zbar (in place)
    float* bufA = Us + TILE*UST;           // double-buffered weight chunks
    float* bufB = bufA + CHUNK_FLOATS;

    const int tid = threadIdx.x;
    const int p0  = blockIdx.x * TILE;

    // ---- load z tile, transposed ----
    {
        const float* zsrc = z2d + (long)p0 * CIN;
        #pragma unroll
        for (int i = 0; i < TILE*CIN/NTHREADS; i++) {
            int idx = tid + i*NTHREADS;
            int px = idx >> 7, c = idx & 127;
            zsT[c*ZST + px] = zsrc[idx];
        }
    }
    // prefetch M chunk 0
    cp16(bufA + tid*4, g_Mcat + tid*4);
    cp16(bufA + tid*4 + 2048, g_Mcat + tid*4 + 2048);
    CP_COMMIT();

    const int pixgrp = tid >> 6;   // 0..7 -> 8 pixels each (phase 1)
    const int lsub   = tid & 63;   // column-pair owner

    // ---- phase 1: U[64][512] = Z[64][128] @ Mcat[128][512] ----
    unsigned long long acc[32];    // [px 8][head 4] f32x2 pairs at o = k*128 + 2*lsub
    #pragma unroll
    for (int i = 0; i < 32; i++) acc[i] = 0ull;

    for (int c = 0; c < 16; c++) {          // 16 chunks of 8 k-rows
        CP_WAIT0();
        __syncthreads();                     // chunk c resident; prev buffer free
        float* bufh = (c & 1) ? bufB : bufA;
        if (c < 15) {
            float* nxt = (c & 1) ? bufA : bufB;
            const float* src = g_Mcat + (c+1)*CHUNK_FLOATS;
            cp16(nxt + tid*4, src + tid*4);
            cp16(nxt + tid*4 + 2048, src + tid*4 + 2048);
            CP_COMMIT();
        }
        #pragma unroll
        for (int kk = 0; kk < 8; kk++) {
            const float* zrow = zsT + (c*8+kk)*ZST + pixgrp*8;
            float4 za  = *(const float4*)(zrow);
            float4 zbv = *(const float4*)(zrow + 4);
            unsigned long long zz[8];
            zz[0]=pack2(za.x);  zz[1]=pack2(za.y);  zz[2]=pack2(za.z);  zz[3]=pack2(za.w);
            zz[4]=pack2(zbv.x); zz[5]=pack2(zbv.y); zz[6]=pack2(zbv.z); zz[7]=pack2(zbv.w);
            const float* mrow = bufh + kk*OD + 2*lsub;
            #pragma unroll
            for (int k = 0; k < 4; k++) {
                unsigned long long mv = *(const unsigned long long*)(mrow + k*128);
                #pragma unroll
                for (int px = 0; px < 8; px++)
                    fma2(acc[px*4 + k], zz[px], mv);
            }
        }
    }
    #pragma unroll
    for (int px = 0; px < 8; px++) {
        float* urow = Us + (pixgrp*8 + px)*UST + 2*lsub;
        #pragma unroll
        for (int k = 0; k < 4; k++)
            *(unsigned long long*)(urow + k*128) = acc[px*4 + k];
    }
    __syncthreads();   // U complete; all phase-1 reads of bufA/bufB and zsT done

    // prefetch P chunk 0 into bufA — rides under all of phase 2
    cp16(bufA + tid*4, g_Pcat + tid*4);
    cp16(bufA + tid*4 + 2048, g_Pcat + tid*4 + 2048);
    CP_COMMIT();

    // ---- phase 2: scores (U . z_t), softmax over t, zbar -> Us (in place) ----
    {
        const int lane = tid & 31;
        const int pix  = (tid >> 5) * 4 + (lane & 3);  // conflict-free LDS map
        const int sub  = lane >> 2;                    // 0..7, in-warp reduction group
        const int cb   = sub * 16;
        const float* zt0 = t2d + (long)(p0 + pix) * CIN + cb;

        float s[NT][NH];
        #pragma unroll
        for (int t = 0; t < NT; t++)
            #pragma unroll
            for (int h = 0; h < NH; h++) s[t][h] = 0.f;

        #pragma unroll
        for (int q4 = 0; q4 < 4; q4++) {
            float4 zl[NT];
            #pragma unroll
            for (int t = 0; t < NT; t++)
                zl[t] = *(const float4*)(zt0 + (long)t * NPIX * CIN + q4*4);
            #pragma unroll
            for (int h = 0; h < NH; h++) {
                float4 u = *(const float4*)(Us + pix*UST + h*128 + cb + q4*4);
                #pragma unroll
                for (int t = 0; t < NT; t++)
                    s[t][h] += u.x*zl[t].x + u.y*zl[t].y + u.z*zl[t].z + u.w*zl[t].w;
            }
        }
        #pragma unroll
        for (int t = 0; t < NT; t++)
            #pragma unroll
            for (int h = 0; h < NH; h++) {
                float p = s[t][h];
                p += __shfl_xor_sync(0xffffffffu, p, 4);
                p += __shfl_xor_sync(0xffffffffu, p, 8);
                p += __shfl_xor_sync(0xffffffffu, p, 16);
                s[t][h] = p * SCALE;
            }
        float w[NT][NH];
        #pragma unroll
        for (int h = 0; h < NH; h++) {
            float m = fmaxf(fmaxf(s[0][h], s[1][h]), fmaxf(s[2][h], s[3][h]));
            float e0 = __expf(s[0][h]-m), e1 = __expf(s[1][h]-m);
            float e2 = __expf(s[2][h]-m), e3 = __expf(s[3][h]-m);
            float inv = 1.f / (e0+e1+e2+e3);
            w[0][h]=e0*inv; w[1][h]=e1*inv; w[2][h]=e2*inv; w[3][h]=e3*inv;
        }
        float zb[NH][16];
        #pragma unroll
        for (int h = 0; h < NH; h++)
            #pragma unroll
            for (int q = 0; q < 16; q++) zb[h][q] = 0.f;
        #pragma unroll
        for (int t = 0; t < NT; t++) {
            const float* ztp = zt0 + (long)t * NPIX * CIN;   // L1 hit (second read)
            float4 zl[4];
            #pragma unroll
            for (int q4 = 0; q4 < 4; q4++) zl[q4] = *(const float4*)(ztp + q4*4);
            #pragma unroll
            for (int h = 0; h < NH; h++) {
                float wv = w[t][h];
                #pragma unroll
                for (int q4 = 0; q4 < 4; q4++) {
                    zb[h][q4*4+0] = fmaf(wv, zl[q4].x, zb[h][q4*4+0]);
                    zb[h][q4*4+1] = fmaf(wv, zl[q4].y, zb[h][q4*4+1]);
                    zb[h][q4*4+2] = fmaf(wv, zl[q4].z, zb[h][q4*4+2]);
                    zb[h][q4*4+3] = fmaf(wv, zl[q4].w, zb[h][q4*4+3]);
                }
            }
        }
        #pragma unroll
        for (int h = 0; h < NH; h++) {
            float* urow = Us + pix*UST + h*128 + cb;
            #pragma unroll
            for (int q4 = 0; q4 < 4; q4++)
                *(float4*)(urow + q4*4) = make_float4(zb[h][q4*4+0], zb[h][q4*4+1],
                                                      zb[h][q4*4+2], zb[h][q4*4+3]);
        }
    }

    // ---- phase 3 (split-k, 16-px groups): out[64][128] = zbar[64][512] @ Pcat[512][128] + bo ----
    // Thread map: half = tid>>8 (o-rows split), pxg = (tid&255)>>6 (4 groups x 16 px), ls = tid&63.
    // Each chunk of 32 P-rows: half 0 does rows [0,16), half 1 rows [16,32).
    {
        const int half = tid >> 8;
        const int hsub = tid & 255;
        const int pxg  = hsub >> 6;     // 0..3 -> 16 px each
        const int ls   = hsub & 63;     // column-pair owner
        float* red = zsT;               // reduction buffer [64][128] (zsT dead)

        unsigned long long oacc[16];
        #pragma unroll
        for (int px = 0; px < 16; px++) oacc[px] = 0ull;

        for (int c = 0; c < 16; c++) {      // 16 chunks of 32 P-rows
            CP_WAIT0();
            __syncthreads();                 // chunk c resident; zbar visible (c==0)
            float* bufh = (c & 1) ? bufB : bufA;
            if (c < 15) {
                float* nxt = (c & 1) ? bufA : bufB;
                const float* src = g_Pcat + (c+1)*CHUNK_FLOATS;
                cp16(nxt + tid*4, src + tid*4);
                cp16(nxt + tid*4 + 2048, src + tid*4 + 2048);
                CP_COMMIT();
            }
            const int r0 = half * 16;        // this half's first row within chunk
            const int o0 = c * 32 + r0;      // global o offset into zbar
            #pragma unroll
            for (int og = 0; og < 4; og++) { // 4 rows per og
                unsigned long long pm[4];
                #pragma unroll
                for (int r = 0; r < 4; r++)
                    pm[r] = *(const unsigned long long*)(bufh + (r0 + og*4 + r)*CIN + 2*ls);
                #pragma unroll
                for (int px = 0; px < 16; px++) {
                    const float4 zq = *(const float4*)(Us + (pxg*16+px)*UST + o0 + og*4);
                    fma2(oacc[px], pack2(zq.x), pm[0]);
                    fma2(oacc[px], pack2(zq.y), pm[1]);
                    fma2(oacc[px], pack2(zq.z), pm[2]);
                    fma2(oacc[px], pack2(zq.w), pm[3]);
                }
            }
        }
        // cross-half reduction through smem (zsT region), then bias + store
        if (half == 1) {
            #pragma unroll
            for (int px = 0; px < 16; px++)
                *(unsigned long long*)(red + (pxg*16+px)*CIN + 2*ls) = oacc[px];
        }
        __syncthreads();
        if (half == 0) {
            unsigned long long bo2 = *(const unsigned long long*)(bo + 2*ls);
            #pragma unroll
            for (int px = 0; px < 16; px++) {
                unsigned long long other =
                    *(const unsigned long long*)(red + (pxg*16+px)*CIN + 2*ls);
                unsigned long long sum = add2(add2(oacc[px], other), bo2);
                long p = p0 + pxg*16 + px;
                *(unsigned long long*)(out + p*CIN + 2*ls) = sum;
            }
        }
    }
}

extern "C" void kernel_launch(void* const* d_in, const int* in_sizes, int n_in,
                              void* d_out, int out_size) {
    const float* z2d = (const float*)d_in[0];
    const float* t2d = (const float*)d_in[1];
    const float* Wq  = (const float*)d_in[2];
    const float* Wk  = (const float*)d_in[3];
    const float* Wv  = (const float*)d_in[4];
    const float* Wo  = (const float*)d_in[5];
    const float* bo  = (const float*)d_in[6];
    float* out = (float*)d_out;

    precompute_MP<<<(CIN*OD + 255)/256, 256>>>(Wq, Wk, Wv, Wo);

    cudaFuncSetAttribute(attn_fused, cudaFuncAttributeMaxDynamicSharedMemorySize,
                         SMEM_FLOATS * (int)sizeof(float));
    attn_fused<<<NPIX/TILE, NTHREADS, SMEM_FLOATS * sizeof(float)>>>(z2d, t2d, bo, out);
}

// round 13
// speedup vs baseline: 1.0569x; 1.0014x over previous
#include <cuda_runtime.h>

#define NPIX 65536
#define CIN 128
#define NH 4
#define NT 4
#define OD 512            // NH * 128 folded dimension
#define TILE 64           // pixels per block
#define NTHREADS 512
#define ZST 68            // zsT row stride (16B-aligned rows)
#define UST 516           // Us row stride
#define CHUNK_FLOATS 4096 // 8 rows x 512 (phase 1) / 32 rows x 128 (phase 3)
#define SMEM_FLOATS (CIN*ZST + TILE*UST + 2*CHUNK_FLOATS)
#define SCALE 0.08838834764831845f   // 1/sqrt(128)

// Folded weights (precomputed each call; no caching)
__device__ float g_Mcat[CIN*OD];   // [c1][o], o = h*128 + c2 : Wq_h^T Wk_h
__device__ float g_Pcat[OD*CIN];   // [o][d]                  : Wo_h Wv_h

__global__ void precompute_MP(const float* __restrict__ Wq, const float* __restrict__ Wk,
                              const float* __restrict__ Wv, const float* __restrict__ Wo) {
    int idx = blockIdx.x * blockDim.x + threadIdx.x;
    if (idx >= CIN*OD) return;
    {
        int c1 = idx >> 9;
        int o  = idx & (OD-1);
        int h = o >> 7, c2 = o & 127;
        float s = 0.f;
        #pragma unroll 4
        for (int cc = 0; cc < 64; cc++) {
            int row = (cc*4 + h) * CIN;
            s += Wq[row + c1] * Wk[row + c2];
        }
        g_Mcat[idx] = s;
    }
    {
        int o = idx >> 7;
        int d = idx & 127;
        int h = o >> 7, c2 = o & 127;
        float s = 0.f;
        #pragma unroll 4
        for (int cc = 0; cc < 64; cc++) {
            int ch = cc*4 + h;
            s += Wo[d*256 + ch] * Wv[ch*CIN + c2];
        }
        g_Pcat[idx] = s;
    }
}

__device__ __forceinline__ unsigned long long pack2(float x) {
    unsigned long long r;
    asm("mov.b64 %0, {%1, %1};" : "=l"(r) : "f"(x));
    return r;
}
__device__ __forceinline__ void fma2(unsigned long long &d, unsigned long long a, unsigned long long b) {
    asm("fma.rn.f32x2 %0, %1, %2, %0;" : "+l"(d) : "l"(a), "l"(b));
}
__device__ __forceinline__ unsigned long long add2(unsigned long long a, unsigned long long b) {
    unsigned long long r;
    asm("add.rn.f32x2 %0, %1, %2;" : "=l"(r) : "l"(a), "l"(b));
    return r;
}
__device__ __forceinline__ void cp16(float* dst, const float* src) {
    unsigned s = (unsigned)__cvta_generic_to_shared(dst);
    asm volatile("cp.async.cg.shared.global [%0], [%1], 16;" :: "r"(s), "l"(src));
}
#define CP_COMMIT() asm volatile("cp.async.commit_group;")
#define CP_WAIT0()  asm volatile("cp.async.wait_group 0;")

__global__ void __launch_bounds__(NTHREADS, 1)
attn_fused(const float* __restrict__ z2d, const float* __restrict__ t2d,
           const float* __restrict__ bo, float* __restrict__ out)
{
    extern __shared__ float sm[];
    float* zsT = sm;                       // [CIN][ZST]  transposed z tile; reused as reduction buf in phase 3
    float* Us  = sm + CIN*ZST;             // [TILE][UST] U, later zbar (in place)
    float* bufA = Us + TILE*UST;           // double-buffered weight chunks
    float* bufB = bufA + CHUNK_FLOATS;

    const int tid = threadIdx.x;
    const int p0  = blockIdx.x * TILE;

    // ---- load z tile, transposed ----
    {
        const float* zsrc = z2d + (long)p0 * CIN;
        #pragma unroll
        for (int i = 0; i < TILE*CIN/NTHREADS; i++) {
            int idx = tid + i*NTHREADS;
            int px = idx >> 7, c = idx & 127;
            zsT[c*ZST + px] = zsrc[idx];
        }
    }
    // prefetch M chunk 0
    cp16(bufA + tid*4, g_Mcat + tid*4);
    cp16(bufA + tid*4 + 2048, g_Mcat + tid*4 + 2048);
    CP_COMMIT();

    const int pixgrp = tid >> 6;   // 0..7 -> 8 pixels each (phase 1)
    const int lsub   = tid & 63;   // column-pair owner

    // ---- phase 1: U[64][512] = Z[64][128] @ Mcat[128][512] ----
    unsigned long long acc[32];    // [px 8][head 4] f32x2 pairs at o = k*128 + 2*lsub
    #pragma unroll
    for (int i = 0; i < 32; i++) acc[i] = 0ull;

    for (int c = 0; c < 16; c++) {          // 16 chunks of 8 k-rows
        CP_WAIT0();
        __syncthreads();                     // chunk c resident; prev buffer free
        float* bufh = (c & 1) ? bufB : bufA;
        if (c < 15) {
            float* nxt = (c & 1) ? bufA : bufB;
            const float* src = g_Mcat + (c+1)*CHUNK_FLOATS;
            cp16(nxt + tid*4, src + tid*4);
            cp16(nxt + tid*4 + 2048, src + tid*4 + 2048);
            CP_COMMIT();
        }
        #pragma unroll
        for (int kk = 0; kk < 8; kk++) {
            const float* zrow = zsT + (c*8+kk)*ZST + pixgrp*8;
            float4 za  = *(const float4*)(zrow);
            float4 zbv = *(const float4*)(zrow + 4);
            unsigned long long zz[8];
            zz[0]=pack2(za.x);  zz[1]=pack2(za.y);  zz[2]=pack2(za.z);  zz[3]=pack2(za.w);
            zz[4]=pack2(zbv.x); zz[5]=pack2(zbv.y); zz[6]=pack2(zbv.z); zz[7]=pack2(zbv.w);
            const float* mrow = bufh + kk*OD + 2*lsub;
            #pragma unroll
            for (int k = 0; k < 4; k++) {
                unsigned long long mv = *(const unsigned long long*)(mrow + k*128);
                #pragma unroll
                for (int px = 0; px < 8; px++)
                    fma2(acc[px*4 + k], zz[px], mv);
            }
        }
    }
    #pragma unroll
    for (int px = 0; px < 8; px++) {
        float* urow = Us + (pixgrp*8 + px)*UST + 2*lsub;
        #pragma unroll
        for (int k = 0; k < 4; k++)
            *(unsigned long long*)(urow + k*128) = acc[px*4 + k];
    }
    __syncthreads();   // U complete; all phase-1 reads of bufA/bufB and zsT done

    // prefetch P chunk 0 into bufA — rides under all of phase 2
    cp16(bufA + tid*4, g_Pcat + tid*4);
    cp16(bufA + tid*4 + 2048, g_Pcat + tid*4 + 2048);
    CP_COMMIT();

    // ---- phase 2: scores (U . z_t), softmax over t, zbar -> Us (in place) ----
    {
        const int lane = tid & 31;
        const int pix  = (tid >> 5) * 4 + (lane & 3);  // conflict-free LDS map
        const int sub  = lane >> 2;                    // 0..7, in-warp reduction group
        const int cb   = sub * 16;
        const float* zt0 = t2d + (long)(p0 + pix) * CIN + cb;

        float s[NT][NH];
        #pragma unroll
        for (int t = 0; t < NT; t++)
            #pragma unroll
            for (int h = 0; h < NH; h++) s[t][h] = 0.f;

        #pragma unroll
        for (int q4 = 0; q4 < 4; q4++) {
            float4 zl[NT];
            #pragma unroll
            for (int t = 0; t < NT; t++)
                zl[t] = *(const float4*)(zt0 + (long)t * NPIX * CIN + q4*4);
            #pragma unroll
            for (int h = 0; h < NH; h++) {
                float4 u = *(const float4*)(Us + pix*UST + h*128 + cb + q4*4);
                #pragma unroll
                for (int t = 0; t < NT; t++)
                    s[t][h] += u.x*zl[t].x + u.y*zl[t].y + u.z*zl[t].z + u.w*zl[t].w;
            }
        }
        #pragma unroll
        for (int t = 0; t < NT; t++)
            #pragma unroll
            for (int h = 0; h < NH; h++) {
                float p = s[t][h];
                p += __shfl_xor_sync(0xffffffffu, p, 4);
                p += __shfl_xor_sync(0xffffffffu, p, 8);
                p += __shfl_xor_sync(0xffffffffu, p, 16);
                s[t][h] = p * SCALE;
            }
        float w[NT][NH];
        #pragma unroll
        for (int h = 0; h < NH; h++) {
            float m = fmaxf(fmaxf(s[0][h], s[1][h]), fmaxf(s[2][h], s[3][h]));
            float e0 = __expf(s[0][h]-m), e1 = __expf(s[1][h]-m);
            float e2 = __expf(s[2][h]-m), e3 = __expf(s[3][h]-m);
            float inv = 1.f / (e0+e1+e2+e3);
            w[0][h]=e0*inv; w[1][h]=e1*inv; w[2][h]=e2*inv; w[3][h]=e3*inv;
        }
        float zb[NH][16];
        #pragma unroll
        for (int h = 0; h < NH; h++)
            #pragma unroll
            for (int q = 0; q < 16; q++) zb[h][q] = 0.f;
        #pragma unroll
        for (int t = 0; t < NT; t++) {
            const float* ztp = zt0 + (long)t * NPIX * CIN;   // L1 hit (second read)
            float4 zl[4];
            #pragma unroll
            for (int q4 = 0; q4 < 4; q4++) zl[q4] = *(const float4*)(ztp + q4*4);
            #pragma unroll
            for (int h = 0; h < NH; h++) {
                float wv = w[t][h];
                #pragma unroll
                for (int q4 = 0; q4 < 4; q4++) {
                    zb[h][q4*4+0] = fmaf(wv, zl[q4].x, zb[h][q4*4+0]);
                    zb[h][q4*4+1] = fmaf(wv, zl[q4].y, zb[h][q4*4+1]);
                    zb[h][q4*4+2] = fmaf(wv, zl[q4].z, zb[h][q4*4+2]);
                    zb[h][q4*4+3] = fmaf(wv, zl[q4].w, zb[h][q4*4+3]);
                }
            }
        }
        #pragma unroll
        for (int h = 0; h < NH; h++) {
            float* urow = Us + pix*UST + h*128 + cb;
            #pragma unroll
            for (int q4 = 0; q4 < 4; q4++)
                *(float4*)(urow + q4*4) = make_float4(zb[h][q4*4+0], zb[h][q4*4+1],
                                                      zb[h][q4*4+2], zb[h][q4*4+3]);
        }
    }

    // ---- phase 3 (split-k, 16-px groups): out[64][128] = zbar[64][512] @ Pcat[512][128] + bo ----
    // Thread map: half = tid>>8 (o-rows split), pxg = (tid&255)>>6 (4 groups x 16 px), ls = tid&63.
    // Each chunk of 32 P-rows: half 0 does rows [0,16), half 1 rows [16,32).
    {
        const int half = tid >> 8;
        const int hsub = tid & 255;
        const int pxg  = hsub >> 6;     // 0..3 -> 16 px each
        const int ls   = hsub & 63;     // column-pair owner
        float* red = zsT;               // reduction buffer [64][128] (zsT dead)

        unsigned long long oacc[16];
        #pragma unroll
        for (int px = 0; px < 16; px++) oacc[px] = 0ull;

        for (int c = 0; c < 16; c++) {      // 16 chunks of 32 P-rows
            CP_WAIT0();
            __syncthreads();                 // chunk c resident; zbar visible (c==0)
            float* bufh = (c & 1) ? bufB : bufA;
            if (c < 15) {
                float* nxt = (c & 1) ? bufA : bufB;
                const float* src = g_Pcat + (c+1)*CHUNK_FLOATS;
                cp16(nxt + tid*4, src + tid*4);
                cp16(nxt + tid*4 + 2048, src + tid*4 + 2048);
                CP_COMMIT();
            }
            const int r0 = half * 16;        // this half's first row within chunk
            const int o0 = c * 32 + r0;      // global o offset into zbar
            #pragma unroll
            for (int og = 0; og < 4; og++) { // 4 rows per og
                unsigned long long pm[4];
                #pragma unroll
                for (int r = 0; r < 4; r++)
                    pm[r] = *(const unsigned long long*)(bufh + (r0 + og*4 + r)*CIN + 2*ls);
                #pragma unroll
                for (int px = 0; px < 16; px++) {
                    const float4 zq = *(const float4*)(Us + (pxg*16+px)*UST + o0 + og*4);
                    fma2(oacc[px], pack2(zq.x), pm[0]);
                    fma2(oacc[px], pack2(zq.y), pm[1]);
                    fma2(oacc[px], pack2(zq.z), pm[2]);
                    fma2(oacc[px], pack2(zq.w), pm[3]);
                }
            }
        }
        // cross-half reduction through smem (zsT region), then bias + store
        if (half == 1) {
            #pragma unroll
            for (int px = 0; px < 16; px++)
                *(unsigned long long*)(red + (pxg*16+px)*CIN + 2*ls) = oacc[px];
        }
        __syncthreads();
        if (half == 0) {
            unsigned long long bo2 = *(const unsigned long long*)(bo + 2*ls);
            #pragma unroll
            for (int px = 0; px < 16; px++) {
                unsigned long long other =
                    *(const unsigned long long*)(red + (pxg*16+px)*CIN + 2*ls);
                unsigned long long sum = add2(add2(oacc[px], other), bo2);
                long p = p0 + pxg*16 + px;
                *(unsigned long long*)(out + p*CIN + 2*ls) = sum;
            }
        }
    }
}

extern "C" void kernel_launch(void* const* d_in, const int* in_sizes, int n_in,
                              void* d_out, int out_size) {
    const float* z2d = (const float*)d_in[0];
    const float* t2d = (const float*)d_in[1];
    const float* Wq  = (const float*)d_in[2];
    const float* Wk  = (const float*)d_in[3];
    const float* Wv  = (const float*)d_in[4];
    const float* Wo  = (const float*)d_in[5];
    const float* bo  = (const float*)d_in[6];
    float* out = (float*)d_out;

    precompute_MP<<<(CIN*OD + 255)/256, 256>>>(Wq, Wk, Wv, Wo);

    cudaFuncSetAttribute(attn_fused, cudaFuncAttributeMaxDynamicSharedMemorySize,
                         SMEM_FLOATS * (int)sizeof(float));
    attn_fused<<<NPIX/TILE, NTHREADS, SMEM_FLOATS * sizeof(float)>>>(z2d, t2d, bo, out);
}

// round 15
// speedup vs baseline: 1.4867x; 1.4067x over previous
#include <cuda_runtime.h>
#include <cuda_bf16.h>

#define NPIX 65536
#define CIN 128
#define NH 4
#define NT 4
#define OD 512
#define SCALE 0.08838834764831845f   // 1/sqrt(128)

// ---------------- global scratch (device statics; no allocs) ----------------
__device__ __align__(256) float          g_U[(size_t)NPIX * OD];        // 128MB
__device__ __align__(256) unsigned short g_zimg[(size_t)NPIX * 1536];   // 192MB  [px][k'] row-major
__device__ __align__(256) unsigned short g_bM[512 * 384];               // [o][k'] row-major
__device__ __align__(256) unsigned short g_bP[128 * 1536];              // [d][k'] row-major

// ---------------- helpers ----------------
__device__ __forceinline__ unsigned short bfs(float x) {
    __nv_bfloat16 h = __float2bfloat16(x);
    return *reinterpret_cast<unsigned short*>(&h);
}
__device__ __forceinline__ float bff(unsigned short u) {
    __nv_bfloat16 h = *reinterpret_cast<__nv_bfloat16*>(&u);
    return __bfloat162float(h);
}
__device__ __forceinline__ void cp16(unsigned dst_smem, const void* src) {
    asm volatile("cp.async.cg.shared.global [%0], [%1], 16;" :: "r"(dst_smem), "l"(src));
}
#define CP_COMMIT() asm volatile("cp.async.commit_group;")
#define CP_WAIT0()  asm volatile("cp.async.wait_group 0;")
#define CP_WAIT1()  asm volatile("cp.async.wait_group 1;")

#define LDSM4(r, addr) \
    asm volatile("ldmatrix.sync.aligned.m8n8.x4.shared.b16 {%0,%1,%2,%3}, [%4];" \
        : "=r"((r)[0]), "=r"((r)[1]), "=r"((r)[2]), "=r"((r)[3]) : "r"(addr))

#define MMA(c, a, b0, b1) \
    asm volatile("mma.sync.aligned.m16n8k16.row.col.f32.bf16.bf16.f32 " \
        "{%0,%1,%2,%3}, {%4,%5,%6,%7}, {%8,%9}, {%0,%1,%2,%3};" \
        : "+f"((c)[0]), "+f"((c)[1]), "+f"((c)[2]), "+f"((c)[3]) \
        : "r"((a)[0]), "r"((a)[1]), "r"((a)[2]), "r"((a)[3]), "r"(b0), "r"(b1))

// ---------------- kernel 1: fold weights -> bf16 hi/lo row-major images ----------------
__global__ void fold_weights(const float* __restrict__ Wq, const float* __restrict__ Wk,
                             const float* __restrict__ Wv, const float* __restrict__ Wo) {
    int idx = blockIdx.x * blockDim.x + threadIdx.x;
    if (idx >= CIN * OD) return;
    {   // M' rows = o, k = c1 ; pattern [hi | hi | lo] over K'=384
        int c1 = idx >> 9, o = idx & (OD - 1);
        int h = o >> 7, c2 = o & 127;
        float s = 0.f;
        #pragma unroll 4
        for (int cc = 0; cc < 64; cc++) {
            int row = (cc * 4 + h) * CIN;
            s += Wq[row + c1] * Wk[row + c2];
        }
        unsigned short hi = bfs(s);
        unsigned short lo = bfs(s - bff(hi));
        g_bM[(size_t)o * 384 + c1]       = hi;
        g_bM[(size_t)o * 384 + 128 + c1] = hi;
        g_bM[(size_t)o * 384 + 256 + c1] = lo;
    }
    {   // P' rows = d, k = o ; pattern [hi | hi | lo] over K'=1536
        int o = idx >> 7, d = idx & 127;
        int h = o >> 7, c2 = o & 127;
        float s = 0.f;
        #pragma unroll 4
        for (int cc = 0; cc < 64; cc++) {
            int ch = cc * 4 + h;
            s += Wo[d * 256 + ch] * Wv[ch * CIN + c2];
        }
        unsigned short hi = bfs(s);
        unsigned short lo = bfs(s - bff(hi));
        g_bP[(size_t)d * 1536 + o]        = hi;
        g_bP[(size_t)d * 1536 + 512 + o]  = hi;
        g_bP[(size_t)d * 1536 + 1024 + o] = lo;
    }
}

// ---------------- kernel 2: U[128px x 256o] per CTA = Zsplit @ M'^T ----------------
// A resident in smem (stride 392 bf16 = 784B), B double-buffered (stride 72 bf16 = 144B).
#define G1_AST 392
#define G1_BST 72
#define G1_ABYTES (128 * G1_AST * 2)     // 100352
#define G1_BBYTES (256 * G1_BST * 2)     // 36864
#define G1_SMEM (G1_ABYTES + 2 * G1_BBYTES)

__global__ void __launch_bounds__(512, 1)
gemm1(const float* __restrict__ z2d) {
    extern __shared__ char smem[];
    char* As = smem;
    const int tid = threadIdx.x, lane = tid & 31, wid = tid >> 5;
    const int mw = wid & 3, nw = wid >> 2;      // warp grid 4m x 4n, warp tile 32x64
    const int p0 = blockIdx.x * 128;
    const int nb = blockIdx.y;                  // 0/1 -> o cols [nb*256, +256)
    unsigned sA = (unsigned)__cvta_generic_to_shared(smem);
    unsigned sB0 = sA + G1_ABYTES;

    // build resident A = [Zhi | Zlo | Zhi] (K'=384)
    const float* zsrc = z2d + (size_t)p0 * CIN;
    #pragma unroll
    for (int j = 0; j < 8; j++) {
        int u = tid + j * 512;                 // 4096 float4 units
        int row = u >> 5, c = (u & 31) * 4;
        float4 v = *(const float4*)(zsrc + row * CIN + c);
        unsigned short h0 = bfs(v.x), h1 = bfs(v.y), h2 = bfs(v.z), h3 = bfs(v.w);
        unsigned short l0 = bfs(v.x - bff(h0)), l1 = bfs(v.y - bff(h1));
        unsigned short l2 = bfs(v.z - bff(h2)), l3 = bfs(v.w - bff(h3));
        uint2 hu = make_uint2((unsigned)h0 | ((unsigned)h1 << 16),
                              (unsigned)h2 | ((unsigned)h3 << 16));
        uint2 lu = make_uint2((unsigned)l0 | ((unsigned)l1 << 16),
                              (unsigned)l2 | ((unsigned)l3 << 16));
        *(uint2*)(As + row * (G1_AST*2) + c * 2)         = hu;
        *(uint2*)(As + row * (G1_AST*2) + (128 + c) * 2) = lu;
        *(uint2*)(As + row * (G1_AST*2) + (256 + c) * 2) = hu;
    }

    const unsigned short* gB = g_bM + (size_t)nb * 256 * 384;
    // prefetch B chunk 0
    #pragma unroll
    for (int j = 0; j < 4; j++) {
        int i = tid + j * 512;                 // 2048 cp16: row = i>>3, seg = i&7
        int row = i >> 3, seg = i & 7;
        cp16(sB0 + row * 144 + seg * 16, gB + (size_t)row * 384 + seg * 8);
    }
    CP_COMMIT();

    float acc[2][8][4];
    #pragma unroll
    for (int a = 0; a < 2; a++)
        #pragma unroll
        for (int b = 0; b < 8; b++)
            #pragma unroll
            for (int q = 0; q < 4; q++) acc[a][b][q] = 0.f;

    for (int c = 0; c < 6; c++) {
        unsigned sBc = sB0 + (unsigned)(c & 1) * G1_BBYTES;
        if (c < 5) {
            unsigned sBn = sB0 + (unsigned)((c + 1) & 1) * G1_BBYTES;
            const unsigned short* src = gB + (c + 1) * 64;
            #pragma unroll
            for (int j = 0; j < 4; j++) {
                int i = tid + j * 512;
                int row = i >> 3, seg = i & 7;
                cp16(sBn + row * 144 + seg * 16, src + (size_t)row * 384 + seg * 8);
            }
            CP_COMMIT();
            CP_WAIT1();
        } else {
            CP_WAIT0();
        }
        __syncthreads();
        #pragma unroll
        for (int ks = 0; ks < 4; ks++) {
            int kg = c * 64 + ks * 16;
            unsigned a[2][4];
            #pragma unroll
            for (int mf = 0; mf < 2; mf++) {
                unsigned addr = sA + (mw * 32 + mf * 16 + (lane & 15)) * (G1_AST*2)
                                   + (kg + (lane >> 4) * 8) * 2;
                LDSM4(a[mf], addr);
            }
            #pragma unroll
            for (int nf2 = 0; nf2 < 4; nf2++) {
                unsigned b[4];
                int noff = nw * 64 + nf2 * 16 + (lane & 7) + ((lane >> 4) & 1) * 8;
                unsigned baddr = sBc + noff * 144 + ks * 32 + ((lane >> 3) & 1) * 16;
                LDSM4(b, baddr);
                MMA(acc[0][nf2*2],   a[0], b[0], b[1]);
                MMA(acc[0][nf2*2+1], a[0], b[2], b[3]);
                MMA(acc[1][nf2*2],   a[1], b[0], b[1]);
                MMA(acc[1][nf2*2+1], a[1], b[2], b[3]);
            }
        }
        __syncthreads();
    }

    // epilogue -> g_U fp32
    #pragma unroll
    for (int mf = 0; mf < 2; mf++) {
        int row = p0 + mw * 32 + mf * 16 + (lane >> 2);
        #pragma unroll
        for (int nf = 0; nf < 8; nf++) {
            int col = nb * 256 + nw * 64 + nf * 8 + (lane & 3) * 2;
            float* d0 = g_U + (size_t)row * OD + col;
            *(float2*)d0            = make_float2(acc[mf][nf][0], acc[mf][nf][1]);
            *(float2*)(d0 + 8 * OD) = make_float2(acc[mf][nf][2], acc[mf][nf][3]);
        }
    }
}

// ---------------- kernel 3: softmax over T, zbar -> row-major bf16 [hi|lo|hi] ----------------
__global__ void __launch_bounds__(512, 1)
phase2(const float* __restrict__ t2d) {
    const int tid = threadIdx.x;
    const int lane = tid & 31;
    const int pix = (tid >> 5) * 4 + (lane & 3);
    const int sub = lane >> 2;
    const int cb = sub * 16;
    const int pxg = blockIdx.x * 64 + pix;
    const float* zt0 = t2d + (size_t)pxg * CIN + cb;
    const float* Urow = g_U + (size_t)pxg * OD;

    float s[NT][NH];
    #pragma unroll
    for (int t = 0; t < NT; t++)
        #pragma unroll
        for (int h = 0; h < NH; h++) s[t][h] = 0.f;

    #pragma unroll
    for (int q4 = 0; q4 < 4; q4++) {
        float4 zl[NT];
        #pragma unroll
        for (int t = 0; t < NT; t++)
            zl[t] = *(const float4*)(zt0 + (size_t)t * NPIX * CIN + q4 * 4);
        #pragma unroll
        for (int h = 0; h < NH; h++) {
            float4 u = *(const float4*)(Urow + h * 128 + cb + q4 * 4);
            #pragma unroll
            for (int t = 0; t < NT; t++)
                s[t][h] += u.x * zl[t].x + u.y * zl[t].y + u.z * zl[t].z + u.w * zl[t].w;
        }
    }
    #pragma unroll
    for (int t = 0; t < NT; t++)
        #pragma unroll
        for (int h = 0; h < NH; h++) {
            float p = s[t][h];
            p += __shfl_xor_sync(0xffffffffu, p, 4);
            p += __shfl_xor_sync(0xffffffffu, p, 8);
            p += __shfl_xor_sync(0xffffffffu, p, 16);
            s[t][h] = p * SCALE;
        }
    float w[NT][NH];
    #pragma unroll
    for (int h = 0; h < NH; h++) {
        float m = fmaxf(fmaxf(s[0][h], s[1][h]), fmaxf(s[2][h], s[3][h]));
        float e0 = __expf(s[0][h]-m), e1 = __expf(s[1][h]-m);
        float e2 = __expf(s[2][h]-m), e3 = __expf(s[3][h]-m);
        float inv = 1.f / (e0 + e1 + e2 + e3);
        w[0][h]=e0*inv; w[1][h]=e1*inv; w[2][h]=e2*inv; w[3][h]=e3*inv;
    }
    float zb[NH][16];
    #pragma unroll
    for (int h = 0; h < NH; h++)
        #pragma unroll
        for (int q = 0; q < 16; q++) zb[h][q] = 0.f;
    #pragma unroll
    for (int t = 0; t < NT; t++) {
        const float* ztp = zt0 + (size_t)t * NPIX * CIN;
        float4 zl[4];
        #pragma unroll
        for (int q4 = 0; q4 < 4; q4++) zl[q4] = *(const float4*)(ztp + q4 * 4);
        #pragma unroll
        for (int h = 0; h < NH; h++) {
            float wv = w[t][h];
            #pragma unroll
            for (int q4 = 0; q4 < 4; q4++) {
                zb[h][q4*4+0] = fmaf(wv, zl[q4].x, zb[h][q4*4+0]);
                zb[h][q4*4+1] = fmaf(wv, zl[q4].y, zb[h][q4*4+1]);
                zb[h][q4*4+2] = fmaf(wv, zl[q4].z, zb[h][q4*4+2]);
                zb[h][q4*4+3] = fmaf(wv, zl[q4].w, zb[h][q4*4+3]);
            }
        }
    }
    unsigned short* img = g_zimg + (size_t)pxg * 1536;
    #pragma unroll
    for (int h = 0; h < NH; h++) {
        const int k0 = h * 128 + cb;
        unsigned hw[8], lw[8];
        #pragma unroll
        for (int j = 0; j < 8; j++) {
            float a = zb[h][2*j], b = zb[h][2*j+1];
            unsigned short ha = bfs(a), hb = bfs(b);
            unsigned short la = bfs(a - bff(ha)), lb = bfs(b - bff(hb));
            hw[j] = (unsigned)ha | ((unsigned)hb << 16);
            lw[j] = (unsigned)la | ((unsigned)lb << 16);
        }
        *(uint4*)(img + k0)            = make_uint4(hw[0], hw[1], hw[2], hw[3]);
        *(uint4*)(img + k0 + 8)        = make_uint4(hw[4], hw[5], hw[6], hw[7]);
        *(uint4*)(img + 512 + k0)      = make_uint4(lw[0], lw[1], lw[2], lw[3]);
        *(uint4*)(img + 512 + k0 + 8)  = make_uint4(lw[4], lw[5], lw[6], lw[7]);
        *(uint4*)(img + 1024 + k0)     = make_uint4(hw[0], hw[1], hw[2], hw[3]);
        *(uint4*)(img + 1024 + k0 + 8) = make_uint4(hw[4], hw[5], hw[6], hw[7]);
    }
}

// ---------------- kernel 4: out[128px x 128d] per CTA = zbar' @ P'^T + bo ----------------
#define G2_ST 72
#define G2_TBYTES (128 * G2_ST * 2)      // 18432 per tile buffer
#define G2_SMEM (4 * G2_TBYTES)          // A0,A1,B0,B1 = 73728

__global__ void __launch_bounds__(256, 2)
gemm2(const float* __restrict__ bo, float* __restrict__ out) {
    extern __shared__ char smem[];
    const int tid = threadIdx.x, lane = tid & 31, wid = tid >> 5;
    const int mw = wid & 3, nw = wid >> 2;      // warp grid 4m x 2n, warp tile 32x64
    const int p0 = blockIdx.x * 128;
    unsigned sA0 = (unsigned)__cvta_generic_to_shared(smem);
    unsigned sB0 = sA0 + 2 * G2_TBYTES;

    const unsigned short* gA = g_zimg + (size_t)p0 * 1536;
    const unsigned short* gB = g_bP;

    // prefetch chunk 0 (A and B)
    #pragma unroll
    for (int j = 0; j < 4; j++) {
        int i = tid + j * 256;                 // 1024 cp16 each
        int row = i >> 3, seg = i & 7;
        cp16(sA0 + row * 144 + seg * 16, gA + (size_t)row * 1536 + seg * 8);
        cp16(sB0 + row * 144 + seg * 16, gB + (size_t)row * 1536 + seg * 8);
    }
    CP_COMMIT();

    float acc[2][8][4];
    #pragma unroll
    for (int a = 0; a < 2; a++)
        #pragma unroll
        for (int b = 0; b < 8; b++)
            #pragma unroll
            for (int q = 0; q < 4; q++) acc[a][b][q] = 0.f;

    for (int c = 0; c < 24; c++) {
        unsigned sAc = sA0 + (unsigned)(c & 1) * G2_TBYTES;
        unsigned sBc = sB0 + (unsigned)(c & 1) * G2_TBYTES;
        if (c < 23) {
            unsigned sAn = sA0 + (unsigned)((c + 1) & 1) * G2_TBYTES;
            unsigned sBn = sB0 + (unsigned)((c + 1) & 1) * G2_TBYTES;
            const unsigned short* asrc = gA + (c + 1) * 64;
            const unsigned short* bsrc = gB + (c + 1) * 64;
            #pragma unroll
            for (int j = 0; j < 4; j++) {
                int i = tid + j * 256;
                int row = i >> 3, seg = i & 7;
                cp16(sAn + row * 144 + seg * 16, asrc + (size_t)row * 1536 + seg * 8);
                cp16(sBn + row * 144 + seg * 16, bsrc + (size_t)row * 1536 + seg * 8);
            }
            CP_COMMIT();
            CP_WAIT1();
        } else {
            CP_WAIT0();
        }
        __syncthreads();
        #pragma unroll
        for (int ks = 0; ks < 4; ks++) {
            unsigned a[2][4];
            #pragma unroll
            for (int mf = 0; mf < 2; mf++) {
                unsigned addr = sAc + (mw * 32 + mf * 16 + (lane & 15)) * 144
                                    + ks * 32 + (lane >> 4) * 16;
                LDSM4(a[mf], addr);
            }
            #pragma unroll
            for (int nf2 = 0; nf2 < 4; nf2++) {
                unsigned b[4];
                int noff = nw * 64 + nf2 * 16 + (lane & 7) + ((lane >> 4) & 1) * 8;
                unsigned baddr = sBc + noff * 144 + ks * 32 + ((lane >> 3) & 1) * 16;
                LDSM4(b, baddr);
                MMA(acc[0][nf2*2],   a[0], b[0], b[1]);
                MMA(acc[0][nf2*2+1], a[0], b[2], b[3]);
                MMA(acc[1][nf2*2],   a[1], b[0], b[1]);
                MMA(acc[1][nf2*2+1], a[1], b[2], b[3]);
            }
        }
        __syncthreads();
    }

    // epilogue -> out + bo
    #pragma unroll
    for (int mf = 0; mf < 2; mf++) {
        int row = p0 + mw * 32 + mf * 16 + (lane >> 2);
        #pragma unroll
        for (int nf = 0; nf < 8; nf++) {
            int col = nw * 64 + nf * 8 + (lane & 3) * 2;
            float2 b2 = *(const float2*)(bo + col);
            float* d0 = out + (size_t)row * CIN + col;
            *(float2*)d0             = make_float2(acc[mf][nf][0] + b2.x, acc[mf][nf][1] + b2.y);
            *(float2*)(d0 + 8 * CIN) = make_float2(acc[mf][nf][2] + b2.x, acc[mf][nf][3] + b2.y);
        }
    }
}

// ---------------- launch ----------------
extern "C" void kernel_launch(void* const* d_in, const int* in_sizes, int n_in,
                              void* d_out, int out_size) {
    const float* z2d = (const float*)d_in[0];
    const float* t2d = (const float*)d_in[1];
    const float* Wq  = (const float*)d_in[2];
    const float* Wk  = (const float*)d_in[3];
    const float* Wv  = (const float*)d_in[4];
    const float* Wo  = (const float*)d_in[5];
    const float* bo  = (const float*)d_in[6];
    float* out = (float*)d_out;

    cudaFuncSetAttribute(gemm1, cudaFuncAttributeMaxDynamicSharedMemorySize, G1_SMEM);
    cudaFuncSetAttribute(gemm2, cudaFuncAttributeMaxDynamicSharedMemorySize, G2_SMEM);

    fold_weights<<<(CIN * OD + 255) / 256, 256>>>(Wq, Wk, Wv, Wo);
    gemm1<<<dim3(NPIX / 128, 2), 512, G1_SMEM>>>(z2d);
    phase2<<<NPIX / 64, 512>>>(t2d);
    gemm2<<<NPIX / 128, 256, G2_SMEM>>>(bo, out);
}

// round 16
// speedup vs baseline: 1.5812x; 1.0635x over previous
#include <cuda_runtime.h>
#include <cuda_bf16.h>

#define NPIX 65536
#define CIN 128
#define NH 4
#define NT 4
#define OD 512
#define SCALE 0.08838834764831845f   // 1/sqrt(128)

// ---------------- global scratch (device statics; no allocs) ----------------
__device__ __align__(256) unsigned short g_zimg[(size_t)NPIX * 1024];   // [px][k'] row-major, [hi|lo]
__device__ __align__(256) unsigned short g_bM[512 * 384];               // [o][k'] row-major [Hi|Hi|Lo]
__device__ __align__(256) unsigned short g_bP[128 * 1536];              // [d][k'] row-major [Hi|Hi|Lo]

// ---------------- helpers ----------------
__device__ __forceinline__ unsigned short bfs(float x) {
    __nv_bfloat16 h = __float2bfloat16(x);
    return *reinterpret_cast<unsigned short*>(&h);
}
__device__ __forceinline__ float bff(unsigned short u) {
    __nv_bfloat16 h = *reinterpret_cast<__nv_bfloat16*>(&u);
    return __bfloat162float(h);
}
__device__ __forceinline__ void cp16(unsigned dst_smem, const void* src) {
    asm volatile("cp.async.cg.shared.global [%0], [%1], 16;" :: "r"(dst_smem), "l"(src));
}
#define CP_COMMIT() asm volatile("cp.async.commit_group;")
#define CP_WAIT0()  asm volatile("cp.async.wait_group 0;")
#define CP_WAIT1()  asm volatile("cp.async.wait_group 1;")

#define LDSM4(r, addr) \
    asm volatile("ldmatrix.sync.aligned.m8n8.x4.shared.b16 {%0,%1,%2,%3}, [%4];" \
        : "=r"((r)[0]), "=r"((r)[1]), "=r"((r)[2]), "=r"((r)[3]) : "r"(addr))

#define MMA(c, a, b0, b1) \
    asm volatile("mma.sync.aligned.m16n8k16.row.col.f32.bf16.bf16.f32 " \
        "{%0,%1,%2,%3}, {%4,%5,%6,%7}, {%8,%9}, {%0,%1,%2,%3};" \
        : "+f"((c)[0]), "+f"((c)[1]), "+f"((c)[2]), "+f"((c)[3]) \
        : "r"((a)[0]), "r"((a)[1]), "r"((a)[2]), "r"((a)[3]), "r"(b0), "r"(b1))

// ---------------- kernel 1: fold weights -> bf16 hi/lo row-major images ----------------
__global__ void fold_weights(const float* __restrict__ Wq, const float* __restrict__ Wk,
                             const float* __restrict__ Wv, const float* __restrict__ Wo) {
    int idx = blockIdx.x * blockDim.x + threadIdx.x;
    if (idx >= CIN * OD) return;
    {   // M' rows = o, k = c1 ; pattern [Hi | Hi | Lo] over K'=384
        int c1 = idx >> 9, o = idx & (OD - 1);
        int h = o >> 7, c2 = o & 127;
        float s = 0.f;
        #pragma unroll 4
        for (int cc = 0; cc < 64; cc++) {
            int row = (cc * 4 + h) * CIN;
            s += Wq[row + c1] * Wk[row + c2];
        }
        unsigned short hi = bfs(s);
        unsigned short lo = bfs(s - bff(hi));
        g_bM[(size_t)o * 384 + c1]       = hi;
        g_bM[(size_t)o * 384 + 128 + c1] = hi;
        g_bM[(size_t)o * 384 + 256 + c1] = lo;
    }
    {   // P' rows = d, k = o ; pattern [Hi | Hi | Lo] over K'=1536
        int o = idx >> 7, d = idx & 127;
        int h = o >> 7, c2 = o & 127;
        float s = 0.f;
        #pragma unroll 4
        for (int cc = 0; cc < 64; cc++) {
            int ch = cc * 4 + h;
            s += Wo[d * 256 + ch] * Wv[ch * CIN + c2];
        }
        unsigned short hi = bfs(s);
        unsigned short lo = bfs(s - bff(hi));
        g_bP[(size_t)d * 1536 + o]        = hi;
        g_bP[(size_t)d * 1536 + 512 + o]  = hi;
        g_bP[(size_t)d * 1536 + 1024 + o] = lo;
    }
}

// ---------------- kernel 2 (fused): U = Zsplit @ M'^T in smem, softmax, zbar -> g_zimg ----------------
// CTA = 64 px x 512 o, K'=384. A resident (stride 392 bf16), B double-buffered (stride 72 bf16).
// U overlays B buffers after the MMA loop ([64][516] fp32).
#define F_AST 392
#define F_ABYTES (64 * F_AST * 2)        // 50176
#define F_BBYTES (512 * 72 * 2)          // 73728
#define F_SMEM (F_ABYTES + 2 * F_BBYTES) // 197632
#define UST 516

__global__ void __launch_bounds__(512, 1)
uattn(const float* __restrict__ z2d, const float* __restrict__ t2d) {
    extern __shared__ char smem[];
    char* As = smem;
    float* Us = (float*)(smem + F_ABYTES);   // overlay on B buffers (post-MMA)
    const int tid = threadIdx.x, lane = tid & 31, wid = tid >> 5;
    const int mw = wid & 1, nw = wid >> 1;   // warp grid 2m x 8n, warp tile 32x64
    const int p0 = blockIdx.x * 64;
    unsigned sA = (unsigned)__cvta_generic_to_shared(smem);
    unsigned sB0 = sA + F_ABYTES;

    // build resident A = [Zhi | Zlo | Zhi] (64 px, K'=384)
    const float* zsrc = z2d + (size_t)p0 * CIN;
    #pragma unroll
    for (int j = 0; j < 4; j++) {
        int u = tid + j * 512;               // 2048 float4 units
        int row = u >> 5, c = (u & 31) * 4;
        float4 v = *(const float4*)(zsrc + row * CIN + c);
        unsigned short h0 = bfs(v.x), h1 = bfs(v.y), h2 = bfs(v.z), h3 = bfs(v.w);
        unsigned short l0 = bfs(v.x - bff(h0)), l1 = bfs(v.y - bff(h1));
        unsigned short l2 = bfs(v.z - bff(h2)), l3 = bfs(v.w - bff(h3));
        uint2 hu = make_uint2((unsigned)h0 | ((unsigned)h1 << 16),
                              (unsigned)h2 | ((unsigned)h3 << 16));
        uint2 lu = make_uint2((unsigned)l0 | ((unsigned)l1 << 16),
                              (unsigned)l2 | ((unsigned)l3 << 16));
        *(uint2*)(As + row * (F_AST*2) + c * 2)         = hu;
        *(uint2*)(As + row * (F_AST*2) + (128 + c) * 2) = lu;
        *(uint2*)(As + row * (F_AST*2) + (256 + c) * 2) = hu;
    }

    // prefetch B chunk 0 (512 o-rows x 64 k)
    #pragma unroll
    for (int j = 0; j < 8; j++) {
        int i = tid + j * 512;               // 4096 cp16: row = i>>3, seg = i&7
        int row = i >> 3, seg = i & 7;
        cp16(sB0 + row * 144 + seg * 16, g_bM + (size_t)row * 384 + seg * 8);
    }
    CP_COMMIT();

    float acc[2][8][4];
    #pragma unroll
    for (int a = 0; a < 2; a++)
        #pragma unroll
        for (int b = 0; b < 8; b++)
            #pragma unroll
            for (int q = 0; q < 4; q++) acc[a][b][q] = 0.f;

    for (int c = 0; c < 6; c++) {
        unsigned sBc = sB0 + (unsigned)(c & 1) * F_BBYTES;
        if (c < 5) {
            unsigned sBn = sB0 + (unsigned)((c + 1) & 1) * F_BBYTES;
            const unsigned short* src = g_bM + (c + 1) * 64;
            #pragma unroll
            for (int j = 0; j < 8; j++) {
                int i = tid + j * 512;
                int row = i >> 3, seg = i & 7;
                cp16(sBn + row * 144 + seg * 16, src + (size_t)row * 384 + seg * 8);
            }
            CP_COMMIT();
            CP_WAIT1();
        } else {
            CP_WAIT0();
        }
        __syncthreads();
        #pragma unroll
        for (int ks = 0; ks < 4; ks++) {
            int kg = c * 64 + ks * 16;
            unsigned a[2][4];
            #pragma unroll
            for (int mf = 0; mf < 2; mf++) {
                unsigned addr = sA + (mw * 32 + mf * 16 + (lane & 15)) * (F_AST*2)
                                   + (kg + (lane >> 4) * 8) * 2;
                LDSM4(a[mf], addr);
            }
            #pragma unroll
            for (int nf2 = 0; nf2 < 4; nf2++) {
                unsigned b[4];
                int noff = nw * 64 + nf2 * 16 + (lane & 7) + ((lane >> 4) & 1) * 8;
                unsigned baddr = sBc + noff * 144 + ks * 32 + ((lane >> 3) & 1) * 16;
                LDSM4(b, baddr);
                MMA(acc[0][nf2*2],   a[0], b[0], b[1]);
                MMA(acc[0][nf2*2+1], a[0], b[2], b[3]);
                MMA(acc[1][nf2*2],   a[1], b[0], b[1]);
                MMA(acc[1][nf2*2+1], a[1], b[2], b[3]);
            }
        }
        __syncthreads();
    }

    // stage U into smem (overlay on B buffers — all MMA reads done)
    #pragma unroll
    for (int mf = 0; mf < 2; mf++) {
        int row = mw * 32 + mf * 16 + (lane >> 2);
        #pragma unroll
        for (int nf = 0; nf < 8; nf++) {
            int col = nw * 64 + nf * 8 + (lane & 3) * 2;
            float* d0 = Us + (size_t)row * UST + col;
            *(float2*)d0            = make_float2(acc[mf][nf][0], acc[mf][nf][1]);
            *(float2*)(d0 + 8 * UST) = make_float2(acc[mf][nf][2], acc[mf][nf][3]);
        }
    }
    __syncthreads();

    // ---- phase 2: scores, softmax over T, zbar -> g_zimg as [hi|lo] (K'=1024) ----
    {
        const int pix = (tid >> 5) * 4 + (lane & 3);   // 0..63
        const int sub = lane >> 2;                     // 0..7
        const int cb = sub * 16;
        const int pxg = p0 + pix;
        const float* zt0 = t2d + (size_t)pxg * CIN + cb;
        const float* Urow = Us + (size_t)pix * UST;

        float s[NT][NH];
        #pragma unroll
        for (int t = 0; t < NT; t++)
            #pragma unroll
            for (int h = 0; h < NH; h++) s[t][h] = 0.f;

        #pragma unroll
        for (int q4 = 0; q4 < 4; q4++) {
            float4 zl[NT];
            #pragma unroll
            for (int t = 0; t < NT; t++)
                zl[t] = *(const float4*)(zt0 + (size_t)t * NPIX * CIN + q4 * 4);
            #pragma unroll
            for (int h = 0; h < NH; h++) {
                float4 u = *(const float4*)(Urow + h * 128 + cb + q4 * 4);
                #pragma unroll
                for (int t = 0; t < NT; t++)
                    s[t][h] += u.x * zl[t].x + u.y * zl[t].y + u.z * zl[t].z + u.w * zl[t].w;
            }
        }
        #pragma unroll
        for (int t = 0; t < NT; t++)
            #pragma unroll
            for (int h = 0; h < NH; h++) {
                float p = s[t][h];
                p += __shfl_xor_sync(0xffffffffu, p, 4);
                p += __shfl_xor_sync(0xffffffffu, p, 8);
                p += __shfl_xor_sync(0xffffffffu, p, 16);
                s[t][h] = p * SCALE;
            }
        float w[NT][NH];
        #pragma unroll
        for (int h = 0; h < NH; h++) {
            float m = fmaxf(fmaxf(s[0][h], s[1][h]), fmaxf(s[2][h], s[3][h]));
            float e0 = __expf(s[0][h]-m), e1 = __expf(s[1][h]-m);
            float e2 = __expf(s[2][h]-m), e3 = __expf(s[3][h]-m);
            float inv = 1.f / (e0 + e1 + e2 + e3);
            w[0][h]=e0*inv; w[1][h]=e1*inv; w[2][h]=e2*inv; w[3][h]=e3*inv;
        }
        float zb[NH][16];
        #pragma unroll
        for (int h = 0; h < NH; h++)
            #pragma unroll
            for (int q = 0; q < 16; q++) zb[h][q] = 0.f;
        #pragma unroll
        for (int t = 0; t < NT; t++) {
            const float* ztp = zt0 + (size_t)t * NPIX * CIN;
            float4 zl[4];
            #pragma unroll
            for (int q4 = 0; q4 < 4; q4++) zl[q4] = *(const float4*)(ztp + q4 * 4);
            #pragma unroll
            for (int h = 0; h < NH; h++) {
                float wv = w[t][h];
                #pragma unroll
                for (int q4 = 0; q4 < 4; q4++) {
                    zb[h][q4*4+0] = fmaf(wv, zl[q4].x, zb[h][q4*4+0]);
                    zb[h][q4*4+1] = fmaf(wv, zl[q4].y, zb[h][q4*4+1]);
                    zb[h][q4*4+2] = fmaf(wv, zl[q4].z, zb[h][q4*4+2]);
                    zb[h][q4*4+3] = fmaf(wv, zl[q4].w, zb[h][q4*4+3]);
                }
            }
        }
        unsigned short* img = g_zimg + (size_t)pxg * 1024;
        #pragma unroll
        for (int h = 0; h < NH; h++) {
            const int k0 = h * 128 + cb;
            unsigned hw[8], lw[8];
            #pragma unroll
            for (int j = 0; j < 8; j++) {
                float a = zb[h][2*j], b = zb[h][2*j+1];
                unsigned short ha = bfs(a), hb = bfs(b);
                unsigned short la = bfs(a - bff(ha)), lb = bfs(b - bff(hb));
                hw[j] = (unsigned)ha | ((unsigned)hb << 16);
                lw[j] = (unsigned)la | ((unsigned)lb << 16);
            }
            *(uint4*)(img + k0)           = make_uint4(hw[0], hw[1], hw[2], hw[3]);
            *(uint4*)(img + k0 + 8)       = make_uint4(hw[4], hw[5], hw[6], hw[7]);
            *(uint4*)(img + 512 + k0)     = make_uint4(lw[0], lw[1], lw[2], lw[3]);
            *(uint4*)(img + 512 + k0 + 8) = make_uint4(lw[4], lw[5], lw[6], lw[7]);
        }
    }
}

// ---------------- kernel 3: out[128px x 128d] = zbar' @ P'^T + bo  (3-stage pipeline) ----------------
// A image is [hi|lo] (K'=1024); term schedule re-reads hi for the hi*Lo product:
//   c in [0,8):   A hi_c   x B Hi_c
//   c in [8,16):  A lo_c   x B Hi_c       (B segment 2 duplicates Hi)
//   c in [16,24): A hi_c   x B Lo_c
#define G2_TB 18432                       // one 128 x 64k bf16 tile (stride 144B)
#define G2_SMEM (6 * G2_TB)               // 3 stages x (A + B)

__global__ void __launch_bounds__(256, 2)
gemm2(const float* __restrict__ bo, float* __restrict__ out) {
    extern __shared__ char smem[];
    const int tid = threadIdx.x, lane = tid & 31, wid = tid >> 5;
    const int mw = wid & 3, nw = wid >> 2;      // warp grid 4m x 2n, warp tile 32x64
    const int p0 = blockIdx.x * 128;
    unsigned sbase = (unsigned)__cvta_generic_to_shared(smem);

    const unsigned short* gA = g_zimg + (size_t)p0 * 1024;
    const unsigned short* gB = g_bP;

    auto issue = [&](int c) {
        int stage = c % 3;
        unsigned sAc = sbase + (unsigned)stage * (2 * G2_TB);
        unsigned sBc = sAc + G2_TB;
        int ao = (c < 8) ? c * 64 : (c < 16) ? 512 + (c - 8) * 64 : (c - 16) * 64;
        const unsigned short* asrc = gA + ao;
        const unsigned short* bsrc = gB + c * 64;
        #pragma unroll
        for (int j = 0; j < 4; j++) {
            int i = tid + j * 256;               // 1024 cp16 each
            int row = i >> 3, seg = i & 7;
            cp16(sAc + row * 144 + seg * 16, asrc + (size_t)row * 1024 + seg * 8);
            cp16(sBc + row * 144 + seg * 16, bsrc + (size_t)row * 1536 + seg * 8);
        }
        CP_COMMIT();
    };

    issue(0);
    issue(1);

    float acc[2][8][4];
    #pragma unroll
    for (int a = 0; a < 2; a++)
        #pragma unroll
        for (int b = 0; b < 8; b++)
            #pragma unroll
            for (int q = 0; q < 4; q++) acc[a][b][q] = 0.f;

    for (int c = 0; c < 24; c++) {
        if (c < 23) { CP_WAIT1(); } else { CP_WAIT0(); }
        __syncthreads();
        if (c + 2 < 24) issue(c + 2);
        int stage = c % 3;
        unsigned sAc = sbase + (unsigned)stage * (2 * G2_TB);
        unsigned sBc = sAc + G2_TB;
        #pragma unroll
        for (int ks = 0; ks < 4; ks++) {
            unsigned a[2][4];
            #pragma unroll
            for (int mf = 0; mf < 2; mf++) {
                unsigned addr = sAc + (mw * 32 + mf * 16 + (lane & 15)) * 144
                                    + ks * 32 + (lane >> 4) * 16;
                LDSM4(a[mf], addr);
            }
            #pragma unroll
            for (int nf2 = 0; nf2 < 4; nf2++) {
                unsigned b[4];
                int noff = nw * 64 + nf2 * 16 + (lane & 7) + ((lane >> 4) & 1) * 8;
                unsigned baddr = sBc + noff * 144 + ks * 32 + ((lane >> 3) & 1) * 16;
                LDSM4(b, baddr);
                MMA(acc[0][nf2*2],   a[0], b[0], b[1]);
                MMA(acc[0][nf2*2+1], a[0], b[2], b[3]);
                MMA(acc[1][nf2*2],   a[1], b[0], b[1]);
                MMA(acc[1][nf2*2+1], a[1], b[2], b[3]);
            }
        }
        __syncthreads();
    }

    // epilogue -> out + bo
    #pragma unroll
    for (int mf = 0; mf < 2; mf++) {
        int row = p0 + mw * 32 + mf * 16 + (lane >> 2);
        #pragma unroll
        for (int nf = 0; nf < 8; nf++) {
            int col = nw * 64 + nf * 8 + (lane & 3) * 2;
            float2 b2 = *(const float2*)(bo + col);
            float* d0 = out + (size_t)row * CIN + col;
            *(float2*)d0             = make_float2(acc[mf][nf][0] + b2.x, acc[mf][nf][1] + b2.y);
            *(float2*)(d0 + 8 * CIN) = make_float2(acc[mf][nf][2] + b2.x, acc[mf][nf][3] + b2.y);
        }
    }
}

// ---------------- launch ----------------
extern "C" void kernel_launch(void* const* d_in, const int* in_sizes, int n_in,
                              void* d_out, int out_size) {
    const float* z2d = (const float*)d_in[0];
    const float* t2d = (const float*)d_in[1];
    const float* Wq  = (const float*)d_in[2];
    const float* Wk  = (const float*)d_in[3];
    const float* Wv  = (const float*)d_in[4];
    const float* Wo  = (const float*)d_in[5];
    const float* bo  = (const float*)d_in[6];
    float* out = (float*)d_out;

    cudaFuncSetAttribute(uattn, cudaFuncAttributeMaxDynamicSharedMemorySize, F_SMEM);
    cudaFuncSetAttribute(gemm2, cudaFuncAttributeMaxDynamicSharedMemorySize, G2_SMEM);

    fold_weights<<<(CIN * OD + 255) / 256, 256>>>(Wq, Wk, Wv, Wo);
    uattn<<<NPIX / 64, 512, F_SMEM>>>(z2d, t2d);
    gemm2<<<NPIX / 128, 256, G2_SMEM>>>(bo, out);
}